// round 3
// baseline (speedup 1.0000x reference)
#include <cuda_runtime.h>

#define D 128
#define MAXN 50000
#define MAXE 800000

// ---------------- scratch (device globals: allocation-free) ----------------
__device__ float g_sums1[(size_t)MAXN * 2 * D];  // [nf-part | ef-part] per node
__device__ float g_sums2[(size_t)MAXN * 2 * D];  // [h1-part | e1-part] per node
__device__ float g_cnt[MAXN];                    // in-degree (raw counts)
__device__ float g_h1[(size_t)MAXN * D];
__device__ float g_pq[(size_t)MAXN * 2 * D];     // [P | Q] per node

// ---------------- helpers ----------------
__device__ __forceinline__ void red_v4(float* addr, float4 v) {
    asm volatile("red.global.add.v4.f32 [%0], {%1,%2,%3,%4};"
                 :: "l"(addr), "f"(v.x), "f"(v.y), "f"(v.z), "f"(v.w)
                 : "memory");
}

// ---------------- kernels ----------------
__global__ void zero_kernel(float* s1, float* s2, float* cnt, int n) {
    int i = blockIdx.x * blockDim.x + threadIdx.x;
    size_t total = (size_t)n * 2 * D;
    for (size_t k = i; k < total; k += (size_t)gridDim.x * blockDim.x) {
        s1[k] = 0.f;
        s2[k] = 0.f;
    }
    if (i < n) cnt[i] = 0.f;
}

// Layer-1 aggregation: scatter-add [nf[u], ef[e]] onto sums1[v], count onto cnt[v].
__global__ void agg1_kernel(const float* __restrict__ nf, const float* __restrict__ ef,
                            const int* __restrict__ u, const int* __restrict__ v,
                            float* __restrict__ sums, float* __restrict__ cnt, int E) {
    int e = blockIdx.x * 8 + (threadIdx.x >> 5);
    int lane = threadIdx.x & 31;
    if (e >= E) return;
    int su = u[e], dv = v[e];
    float4 a = reinterpret_cast<const float4*>(nf + (size_t)su * D)[lane];
    float4 b = reinterpret_cast<const float4*>(ef + (size_t)e * D)[lane];
    float* base = sums + (size_t)dv * 2 * D;
    red_v4(base + lane * 4, a);
    red_v4(base + D + lane * 4, b);
    if (lane == 0) atomicAdd(cnt + dv, 1.0f);
}

// Layer-2 aggregation: e1 = relu(P1[u] + Q1[v] + b1e) computed on the fly,
// scatter-add [h1[u], e1] onto sums2[v].
__global__ void agg2_kernel(const float* __restrict__ h1, const float* __restrict__ pq,
                            const float* __restrict__ be,
                            const int* __restrict__ u, const int* __restrict__ v,
                            float* __restrict__ sums, int E) {
    int e = blockIdx.x * 8 + (threadIdx.x >> 5);
    int lane = threadIdx.x & 31;
    if (e >= E) return;
    int su = u[e], dv = v[e];
    float4 h  = reinterpret_cast<const float4*>(h1 + (size_t)su * D)[lane];
    float4 p  = reinterpret_cast<const float4*>(pq + (size_t)su * 2 * D)[lane];
    float4 q  = reinterpret_cast<const float4*>(pq + (size_t)dv * 2 * D + D)[lane];
    float4 bb = reinterpret_cast<const float4*>(be)[lane];
    float4 e1;
    e1.x = fmaxf(p.x + q.x + bb.x, 0.f);
    e1.y = fmaxf(p.y + q.y + bb.y, 0.f);
    e1.z = fmaxf(p.z + q.z + bb.z, 0.f);
    e1.w = fmaxf(p.w + q.w + bb.w, 0.f);
    float* base = sums + (size_t)dv * 2 * D;
    red_v4(base + lane * 4, h);
    red_v4(base + D + lane * 4, e1);
}

// Final edge output: e2 = relu(P2[u] + Q2[v] + b2e)
__global__ void edge2_kernel(const float* __restrict__ pq, const float* __restrict__ be,
                             const int* __restrict__ u, const int* __restrict__ v,
                             float* __restrict__ out_e, int E) {
    int e = blockIdx.x * 8 + (threadIdx.x >> 5);
    int lane = threadIdx.x & 31;
    if (e >= E) return;
    int su = u[e], dv = v[e];
    float4 p  = reinterpret_cast<const float4*>(pq + (size_t)su * 2 * D)[lane];
    float4 q  = reinterpret_cast<const float4*>(pq + (size_t)dv * 2 * D + D)[lane];
    float4 bb = reinterpret_cast<const float4*>(be)[lane];
    float4 o;
    o.x = fmaxf(p.x + q.x + bb.x, 0.f);
    o.y = fmaxf(p.y + q.y + bb.y, 0.f);
    o.z = fmaxf(p.z + q.z + bb.z, 0.f);
    o.w = fmaxf(p.w + q.w + bb.w, 0.f);
    reinterpret_cast<float4*>(out_e + (size_t)e * D)[lane] = o;
}

// ---------------- tiled fp32 GEMM for the node MLP ----------------
// Y[r, o] = act( A(r,:) . B(o,:) + bias[o] )
// A(r,k): catmode==0 -> A0[r*128 + k]                              (K = 128)
//         catmode==1 -> k<128 ? A0[r*128+k]
//                             : A1[r*256 + (k-128)] / max(cnt[r],1)   (K = 384)
// B row-major with leading dim ldb. When gridDim.y == 2 (PQ mode),
// blockIdx.y selects B half and the output column offset.
#define TM 128
#define TN 128
#define KC 16

__global__ void __launch_bounds__(256, 2)
gemm_kernel(const float* __restrict__ A0, const float* __restrict__ A1,
            const float* __restrict__ cnt,
            const float* __restrict__ B, int ldb,
            const float* __restrict__ bias, int do_relu,
            float* __restrict__ Y, int ldy,
            int M, int K, int catmode) {
    __shared__ float As[KC][TM + 4];
    __shared__ float Ws[KC][TN + 4];
    int tid = threadIdx.x;
    int tx = tid & 15, ty = tid >> 4;
    int row0 = blockIdx.x * TM;
    int ycol = blockIdx.y * D;           // 0 for y==0, 128 for PQ second half
    const float* Bsel = B + (size_t)blockIdx.y * D;  // second half of We rows' columns

    float acc[8][8];
#pragma unroll
    for (int i = 0; i < 8; i++)
#pragma unroll
        for (int j = 0; j < 8; j++) acc[i][j] = 0.f;

    for (int kc = 0; kc < K; kc += KC) {
        // load A tile (transposed into As[k][m])
#pragma unroll
        for (int i = 0; i < 8; i++) {
            int idx = tid + i * 256;
            int r = idx >> 4;
            int c = idx & 15;
            int gr = row0 + r;
            float val = 0.f;
            if (gr < M) {
                int kk = kc + c;
                if (!catmode) {
                    val = A0[(size_t)gr * D + kk];
                } else {
                    if (kk < D) val = A0[(size_t)gr * D + kk];
                    else        val = A1[(size_t)gr * 2 * D + (kk - D)] *
                                      (1.0f / fmaxf(cnt[gr], 1.0f));
                }
            }
            As[c][r] = val;
        }
        // load B tile (Ws[k][o])
#pragma unroll
        for (int i = 0; i < 8; i++) {
            int idx = tid + i * 256;
            int o = idx >> 4;
            int c = idx & 15;
            Ws[c][o] = Bsel[(size_t)o * ldb + kc + c];
        }
        __syncthreads();
#pragma unroll
        for (int k = 0; k < KC; k++) {
            float a[8], bv[8];
            *(float4*)&a[0]  = *(const float4*)&As[k][ty * 8];
            *(float4*)&a[4]  = *(const float4*)&As[k][ty * 8 + 4];
            *(float4*)&bv[0] = *(const float4*)&Ws[k][tx * 8];
            *(float4*)&bv[4] = *(const float4*)&Ws[k][tx * 8 + 4];
#pragma unroll
            for (int i = 0; i < 8; i++)
#pragma unroll
                for (int j = 0; j < 8; j++)
                    acc[i][j] += a[i] * bv[j];
        }
        __syncthreads();
    }

#pragma unroll
    for (int i = 0; i < 8; i++) {
        int gr = row0 + ty * 8 + i;
        if (gr >= M) break;
#pragma unroll
        for (int j = 0; j < 8; j++) {
            int o = tx * 8 + j;
            float val = acc[i][j];
            if (bias) val += bias[o];
            if (do_relu) val = fmaxf(val, 0.f);
            Y[(size_t)gr * ldy + ycol + o] = val;
        }
    }
}

// ---------------- launch ----------------
extern "C" void kernel_launch(void* const* d_in, const int* in_sizes, int n_in,
                              void* d_out, int out_size) {
    const float* nf  = (const float*)d_in[0];
    const float* ef  = (const float*)d_in[1];
    const int*   u   = (const int*)d_in[2];
    const int*   v   = (const int*)d_in[3];
    const float* W1a = (const float*)d_in[4];
    const float* b1a = (const float*)d_in[5];
    const float* W1e = (const float*)d_in[6];
    const float* b1e = (const float*)d_in[7];
    const float* W2a = (const float*)d_in[8];
    const float* b2a = (const float*)d_in[9];
    const float* W2e = (const float*)d_in[10];
    const float* b2e = (const float*)d_in[11];

    int N = in_sizes[0] / D;
    int E = in_sizes[2];

    float* out_h = (float*)d_out;
    float* out_e = out_h + (size_t)N * D;

    float *sums1, *sums2, *cnt, *h1, *pq;
    cudaGetSymbolAddress((void**)&sums1, g_sums1);
    cudaGetSymbolAddress((void**)&sums2, g_sums2);
    cudaGetSymbolAddress((void**)&cnt,   g_cnt);
    cudaGetSymbolAddress((void**)&h1,    g_h1);
    cudaGetSymbolAddress((void**)&pq,    g_pq);

    int eblocks = (E + 7) / 8;
    int mt = (N + TM - 1) / TM;
    dim3 grid1(mt, 1), grid2(mt, 2);

    zero_kernel<<<4096, 256>>>(sums1, sums2, cnt, N);

    // layer 1
    agg1_kernel<<<eblocks, 256>>>(nf, ef, u, v, sums1, cnt, E);
    gemm_kernel<<<grid1, 256>>>(nf, sums1, cnt, W1a, 3 * D, b1a, 1, h1, D, N, 3 * D, 1);
    gemm_kernel<<<grid2, 256>>>(h1, nullptr, nullptr, W1e, 2 * D, nullptr, 0, pq, 2 * D, N, D, 0);

    // layer 2
    agg2_kernel<<<eblocks, 256>>>(h1, pq, b1e, u, v, sums2, E);
    gemm_kernel<<<grid1, 256>>>(h1, sums2, cnt, W2a, 3 * D, b2a, 1, out_h, D, N, 3 * D, 1);
    gemm_kernel<<<grid2, 256>>>(out_h, nullptr, nullptr, W2e, 2 * D, nullptr, 0, pq, 2 * D, N, D, 0);
    edge2_kernel<<<eblocks, 256>>>(pq, b2e, u, v, out_e, E);
}

// round 4
// speedup vs baseline: 1.7432x; 1.7432x over previous
#include <cuda_runtime.h>
#include <cstdint>

#define D 128
#define MAXN 50000
#define MAXE 800000

// ---------------- scratch (device globals: allocation-free) ----------------
__device__ float g_sums1[(size_t)MAXN * 2 * D];  // [nf-part | ef-part] per node
__device__ float g_sums2[(size_t)MAXN * 2 * D];  // [h1-part | e1-part] per node
__device__ float g_cnt[MAXN];                    // in-degree (raw counts)
__device__ float g_h1[(size_t)MAXN * D];
__device__ float g_pq[(size_t)MAXN * 2 * D];     // [P | Q] per node

// ---------------- helpers ----------------
__device__ __forceinline__ void red_v4(float* addr, float4 v) {
    asm volatile("red.global.add.v4.f32 [%0], {%1,%2,%3,%4};"
                 :: "l"(addr), "f"(v.x), "f"(v.y), "f"(v.z), "f"(v.w)
                 : "memory");
}

__device__ __forceinline__ uint32_t f2tf32(float f) {
    uint32_t r;
    asm("cvt.rna.tf32.f32 %0, %1;" : "=r"(r) : "f"(f));
    return r;
}

// ---------------- kernels ----------------
__global__ void zero_kernel(float* s1, float* s2, float* cnt, int n) {
    int i = blockIdx.x * blockDim.x + threadIdx.x;
    size_t total = (size_t)n * 2 * D;
    for (size_t k = i; k < total; k += (size_t)gridDim.x * blockDim.x) {
        s1[k] = 0.f;
        s2[k] = 0.f;
    }
    if (i < n) cnt[i] = 0.f;
}

// Layer-1 aggregation: scatter-add [nf[u], ef[e]] onto sums1[v], count onto cnt[v].
__global__ void agg1_kernel(const float* __restrict__ nf, const float* __restrict__ ef,
                            const int* __restrict__ u, const int* __restrict__ v,
                            float* __restrict__ sums, float* __restrict__ cnt, int E) {
    int e = blockIdx.x * 8 + (threadIdx.x >> 5);
    int lane = threadIdx.x & 31;
    if (e >= E) return;
    int su = u[e], dv = v[e];
    float4 a = reinterpret_cast<const float4*>(nf + (size_t)su * D)[lane];
    float4 b = reinterpret_cast<const float4*>(ef + (size_t)e * D)[lane];
    float* base = sums + (size_t)dv * 2 * D;
    red_v4(base + lane * 4, a);
    red_v4(base + D + lane * 4, b);
    if (lane == 0) atomicAdd(cnt + dv, 1.0f);
}

// Layer-2 aggregation: e1 = relu(P1[u] + Q1[v] + b1e) computed on the fly,
// scatter-add [h1[u], e1] onto sums2[v].
__global__ void agg2_kernel(const float* __restrict__ h1, const float* __restrict__ pq,
                            const float* __restrict__ be,
                            const int* __restrict__ u, const int* __restrict__ v,
                            float* __restrict__ sums, int E) {
    int e = blockIdx.x * 8 + (threadIdx.x >> 5);
    int lane = threadIdx.x & 31;
    if (e >= E) return;
    int su = u[e], dv = v[e];
    float4 h  = reinterpret_cast<const float4*>(h1 + (size_t)su * D)[lane];
    float4 p  = reinterpret_cast<const float4*>(pq + (size_t)su * 2 * D)[lane];
    float4 q  = reinterpret_cast<const float4*>(pq + (size_t)dv * 2 * D + D)[lane];
    float4 bb = reinterpret_cast<const float4*>(be)[lane];
    float4 e1;
    e1.x = fmaxf(p.x + q.x + bb.x, 0.f);
    e1.y = fmaxf(p.y + q.y + bb.y, 0.f);
    e1.z = fmaxf(p.z + q.z + bb.z, 0.f);
    e1.w = fmaxf(p.w + q.w + bb.w, 0.f);
    float* base = sums + (size_t)dv * 2 * D;
    red_v4(base + lane * 4, h);
    red_v4(base + D + lane * 4, e1);
}

// Final edge output: e2 = relu(P2[u] + Q2[v] + b2e)
__global__ void edge2_kernel(const float* __restrict__ pq, const float* __restrict__ be,
                             const int* __restrict__ u, const int* __restrict__ v,
                             float* __restrict__ out_e, int E) {
    int e = blockIdx.x * 8 + (threadIdx.x >> 5);
    int lane = threadIdx.x & 31;
    if (e >= E) return;
    int su = u[e], dv = v[e];
    float4 p  = reinterpret_cast<const float4*>(pq + (size_t)su * 2 * D)[lane];
    float4 q  = reinterpret_cast<const float4*>(pq + (size_t)dv * 2 * D + D)[lane];
    float4 bb = reinterpret_cast<const float4*>(be)[lane];
    float4 o;
    o.x = fmaxf(p.x + q.x + bb.x, 0.f);
    o.y = fmaxf(p.y + q.y + bb.y, 0.f);
    o.z = fmaxf(p.z + q.z + bb.z, 0.f);
    o.w = fmaxf(p.w + q.w + bb.w, 0.f);
    reinterpret_cast<float4*>(out_e + (size_t)e * D)[lane] = o;
}

// ---------------- tf32 tensor-core GEMM for the node MLPs ----------------
// Y[r, ycol+o] = act( A(r,:) . B(o,:) + bias[o] )
// A(r,k): catmode==0 -> A0[r*128 + k]                              (K = 128)
//         catmode==1 -> k<128 ? A0[r*128+k]
//                             : A1[r*256 + (k-128)] / max(cnt[r],1)   (K = 384)
// B row-major, leading dim ldb. gridDim.y==2 selects B column-half + ycol (PQ mode).
// Block tile 128x128, 8 warps = 4(m) x 2(n), warp tile 32x64, mma.m16n8k8 tf32.
#define TM 128
#define KC 16
#define KSTR 20  // smem row stride (floats): bank-conflict-free for frag reads

__global__ void __launch_bounds__(256)
gemm_tf32_kernel(const float* __restrict__ A0, const float* __restrict__ A1,
                 const float* __restrict__ cnt,
                 const float* __restrict__ B, int ldb,
                 const float* __restrict__ bias, int do_relu,
                 float* __restrict__ Y, int ldy,
                 int M, int K, int catmode) {
    __shared__ uint32_t As[TM * KSTR];
    __shared__ uint32_t Bs[TM * KSTR];

    int tid = threadIdx.x;
    int lane = tid & 31;
    int warp = tid >> 5;
    int warp_m = warp & 3;        // 0..3 -> m offset *32
    int warp_n = warp >> 2;       // 0..1 -> n offset *64
    int qrow = lane >> 2;         // 0..7
    int qcol = lane & 3;          // 0..3

    int row0 = blockIdx.x * TM;
    int ycol = blockIdx.y * D;
    const float* Bsel = B + (size_t)blockIdx.y * D;

    float acc[2][8][4];
#pragma unroll
    for (int i = 0; i < 2; i++)
#pragma unroll
        for (int j = 0; j < 8; j++)
#pragma unroll
            for (int q = 0; q < 4; q++) acc[i][j][q] = 0.f;

    int lrow = tid >> 2;          // 0..63
    int lc4  = (tid & 3) * 4;     // 0,4,8,12

    for (int kc = 0; kc < K; kc += KC) {
        // ---- stage A tile (tf32) ----
#pragma unroll
        for (int p = 0; p < 2; p++) {
            int r = lrow + p * 64;
            int gr = row0 + r;
            float4 av = make_float4(0.f, 0.f, 0.f, 0.f);
            if (gr < M) {
                int kk = kc + lc4;
                if (!catmode || kk < D) {
                    av = *reinterpret_cast<const float4*>(A0 + (size_t)gr * D + kk);
                } else {
                    av = *reinterpret_cast<const float4*>(A1 + (size_t)gr * 2 * D + (kk - D));
                    float inv = 1.0f / fmaxf(cnt[gr], 1.0f);
                    av.x *= inv; av.y *= inv; av.z *= inv; av.w *= inv;
                }
            }
            uint32_t* dst = As + r * KSTR + lc4;
            dst[0] = f2tf32(av.x); dst[1] = f2tf32(av.y);
            dst[2] = f2tf32(av.z); dst[3] = f2tf32(av.w);
        }
        // ---- stage B tile (tf32) ----
#pragma unroll
        for (int p = 0; p < 2; p++) {
            int o = lrow + p * 64;
            float4 bv = *reinterpret_cast<const float4*>(Bsel + (size_t)o * ldb + kc + lc4);
            uint32_t* dst = Bs + o * KSTR + lc4;
            dst[0] = f2tf32(bv.x); dst[1] = f2tf32(bv.y);
            dst[2] = f2tf32(bv.z); dst[3] = f2tf32(bv.w);
        }
        __syncthreads();

        // ---- mma over the 16-wide chunk: two k8 steps ----
#pragma unroll
        for (int ks = 0; ks < 2; ks++) {
            int k0 = ks * 8;
            uint32_t af[2][4];
#pragma unroll
            for (int i = 0; i < 2; i++) {
                int mr = warp_m * 32 + i * 16;
                af[i][0] = As[(mr + qrow) * KSTR + k0 + qcol];
                af[i][1] = As[(mr + 8 + qrow) * KSTR + k0 + qcol];
                af[i][2] = As[(mr + qrow) * KSTR + k0 + 4 + qcol];
                af[i][3] = As[(mr + 8 + qrow) * KSTR + k0 + 4 + qcol];
            }
            uint32_t bf[8][2];
#pragma unroll
            for (int j = 0; j < 8; j++) {
                int nr = warp_n * 64 + j * 8;
                bf[j][0] = Bs[(nr + qrow) * KSTR + k0 + qcol];
                bf[j][1] = Bs[(nr + qrow) * KSTR + k0 + 4 + qcol];
            }
#pragma unroll
            for (int i = 0; i < 2; i++)
#pragma unroll
                for (int j = 0; j < 8; j++) {
                    asm volatile(
                        "mma.sync.aligned.m16n8k8.row.col.f32.tf32.tf32.f32 "
                        "{%0,%1,%2,%3}, {%4,%5,%6,%7}, {%8,%9}, {%0,%1,%2,%3};\n"
                        : "+f"(acc[i][j][0]), "+f"(acc[i][j][1]),
                          "+f"(acc[i][j][2]), "+f"(acc[i][j][3])
                        : "r"(af[i][0]), "r"(af[i][1]), "r"(af[i][2]), "r"(af[i][3]),
                          "r"(bf[j][0]), "r"(bf[j][1]));
                }
        }
        __syncthreads();
    }

    // ---- epilogue: bias + relu + store (float2 per half-fragment) ----
#pragma unroll
    for (int i = 0; i < 2; i++) {
#pragma unroll
        for (int j = 0; j < 8; j++) {
            int col = warp_n * 64 + j * 8 + qcol * 2;
            float b0 = bias ? bias[col]     : 0.f;
            float b1 = bias ? bias[col + 1] : 0.f;
            int gr0 = row0 + warp_m * 32 + i * 16 + qrow;
            float v0 = acc[i][j][0] + b0;
            float v1 = acc[i][j][1] + b1;
            float v2 = acc[i][j][2] + b0;
            float v3 = acc[i][j][3] + b1;
            if (do_relu) {
                v0 = fmaxf(v0, 0.f); v1 = fmaxf(v1, 0.f);
                v2 = fmaxf(v2, 0.f); v3 = fmaxf(v3, 0.f);
            }
            if (gr0 < M)
                *reinterpret_cast<float2*>(Y + (size_t)gr0 * ldy + ycol + col) =
                    make_float2(v0, v1);
            if (gr0 + 8 < M)
                *reinterpret_cast<float2*>(Y + (size_t)(gr0 + 8) * ldy + ycol + col) =
                    make_float2(v2, v3);
        }
    }
}

// ---------------- launch ----------------
extern "C" void kernel_launch(void* const* d_in, const int* in_sizes, int n_in,
                              void* d_out, int out_size) {
    const float* nf  = (const float*)d_in[0];
    const float* ef  = (const float*)d_in[1];
    const int*   u   = (const int*)d_in[2];
    const int*   v   = (const int*)d_in[3];
    const float* W1a = (const float*)d_in[4];
    const float* b1a = (const float*)d_in[5];
    const float* W1e = (const float*)d_in[6];
    const float* b1e = (const float*)d_in[7];
    const float* W2a = (const float*)d_in[8];
    const float* b2a = (const float*)d_in[9];
    const float* W2e = (const float*)d_in[10];
    const float* b2e = (const float*)d_in[11];

    int N = in_sizes[0] / D;
    int E = in_sizes[2];

    float* out_h = (float*)d_out;
    float* out_e = out_h + (size_t)N * D;

    float *sums1, *sums2, *cnt, *h1, *pq;
    cudaGetSymbolAddress((void**)&sums1, g_sums1);
    cudaGetSymbolAddress((void**)&sums2, g_sums2);
    cudaGetSymbolAddress((void**)&cnt,   g_cnt);
    cudaGetSymbolAddress((void**)&h1,    g_h1);
    cudaGetSymbolAddress((void**)&pq,    g_pq);

    int eblocks = (E + 7) / 8;
    int mt = (N + TM - 1) / TM;
    dim3 grid1(mt, 1), grid2(mt, 2);

    zero_kernel<<<4096, 256>>>(sums1, sums2, cnt, N);

    // layer 1
    agg1_kernel<<<eblocks, 256>>>(nf, ef, u, v, sums1, cnt, E);
    gemm_tf32_kernel<<<grid1, 256>>>(nf, sums1, cnt, W1a, 3 * D, b1a, 1, h1, D, N, 3 * D, 1);
    gemm_tf32_kernel<<<grid2, 256>>>(h1, nullptr, nullptr, W1e, 2 * D, nullptr, 0, pq, 2 * D, N, D, 0);

    // layer 2
    agg2_kernel<<<eblocks, 256>>>(h1, pq, b1e, u, v, sums2, E);
    gemm_tf32_kernel<<<grid1, 256>>>(h1, sums2, cnt, W2a, 3 * D, b2a, 1, out_h, D, N, 3 * D, 1);
    gemm_tf32_kernel<<<grid2, 256>>>(out_h, nullptr, nullptr, W2e, 2 * D, nullptr, 0, pq, 2 * D, N, D, 0);
    edge2_kernel<<<eblocks, 256>>>(pq, b2e, u, v, out_e, E);
}

// round 5
// speedup vs baseline: 1.9455x; 1.1161x over previous
#include <cuda_runtime.h>
#include <cstdint>

#define D 128
#define MAXN 50000
#define MAXE 800000

// ---------------- scratch (device globals: allocation-free) ----------------
__device__ float g_mean1[(size_t)MAXN * 2 * D];  // [mean nf[u] | mean ef] per node
__device__ float g_mean2[(size_t)MAXN * 2 * D];  // [mean h1[u] | mean e1] per node
__device__ float g_h1[(size_t)MAXN * D];
__device__ float g_pq[(size_t)MAXN * 2 * D];     // [P | Q] per node
__device__ int   g_icnt[MAXN];                   // in-degree histogram
__device__ int   g_rowstart[MAXN + 1];           // CSR row offsets (by dst v)
__device__ int   g_cursor[MAXN];                 // fill cursors
__device__ int   g_eidx[MAXE];                   // edge ids grouped by dst

// ---------------- helpers ----------------
__device__ __forceinline__ uint32_t f2tf32(float f) {
    uint32_t r;
    asm("cvt.rna.tf32.f32 %0, %1;" : "=r"(r) : "f"(f));
    return r;
}

__device__ __forceinline__ void add4(float4& a, float4 b) {
    a.x += b.x; a.y += b.y; a.z += b.z; a.w += b.w;
}

// ---------------- CSR build ----------------
__global__ void zero_icnt_kernel(int* icnt, int n) {
    int i = blockIdx.x * blockDim.x + threadIdx.x;
    if (i < n) icnt[i] = 0;
}

__global__ void hist_kernel(const int* __restrict__ v, int* __restrict__ icnt, int E) {
    int e = blockIdx.x * blockDim.x + threadIdx.x;
    if (e < E) atomicAdd(icnt + v[e], 1);
}

__global__ void scan_kernel(const int* __restrict__ icnt, int* __restrict__ row_start,
                            int* __restrict__ cursor, int n) {
    __shared__ int partial[1024];
    int t = threadIdx.x;
    int chunk = (n + 1023) / 1024;
    int lo = t * chunk;
    int hi = min(lo + chunk, n);
    int s = 0;
    for (int i = lo; i < hi; i++) s += icnt[i];
    partial[t] = s;
    __syncthreads();
    for (int off = 1; off < 1024; off <<= 1) {
        int val = (t >= off) ? partial[t - off] : 0;
        __syncthreads();
        partial[t] += val;
        __syncthreads();
    }
    int base = (t == 0) ? 0 : partial[t - 1];
    for (int i = lo; i < hi; i++) {
        row_start[i] = base;
        cursor[i] = base;
        base += icnt[i];
    }
    if (t == 1023) row_start[n] = partial[1023];
}

__global__ void fill_kernel(const int* __restrict__ v, int* __restrict__ cursor,
                            int* __restrict__ eidx, int E) {
    int e = blockIdx.x * blockDim.x + threadIdx.x;
    if (e < E) {
        int slot = atomicAdd(cursor + v[e], 1);
        eidx[slot] = e;
    }
}

// ---------------- gather aggregation (warp per node) ----------------
// Layer 1: mean over incident edges of [nf[u], ef[e]] -> g_mean1[node]
__global__ void agg1_gather_kernel(const float* __restrict__ nf, const float* __restrict__ ef,
                                   const int* __restrict__ u,
                                   const int* __restrict__ row_start,
                                   const int* __restrict__ eidx,
                                   float* __restrict__ mean, int N) {
    int node = blockIdx.x * 8 + (threadIdx.x >> 5);
    int lane = threadIdx.x & 31;
    if (node >= N) return;
    int rs = row_start[node], re = row_start[node + 1];
    float4 accN = make_float4(0.f, 0.f, 0.f, 0.f);
    float4 accE = make_float4(0.f, 0.f, 0.f, 0.f);
    int j = rs;
    for (; j + 1 < re; j += 2) {
        int e0 = eidx[j], e1 = eidx[j + 1];
        int s0 = u[e0], s1 = u[e1];
        float4 n0 = reinterpret_cast<const float4*>(nf + (size_t)s0 * D)[lane];
        float4 f0 = reinterpret_cast<const float4*>(ef + (size_t)e0 * D)[lane];
        float4 n1 = reinterpret_cast<const float4*>(nf + (size_t)s1 * D)[lane];
        float4 f1 = reinterpret_cast<const float4*>(ef + (size_t)e1 * D)[lane];
        add4(accN, n0); add4(accE, f0);
        add4(accN, n1); add4(accE, f1);
    }
    if (j < re) {
        int e0 = eidx[j];
        int s0 = u[e0];
        add4(accN, reinterpret_cast<const float4*>(nf + (size_t)s0 * D)[lane]);
        add4(accE, reinterpret_cast<const float4*>(ef + (size_t)e0 * D)[lane]);
    }
    float inv = 1.0f / fmaxf((float)(re - rs), 1.0f);
    accN.x *= inv; accN.y *= inv; accN.z *= inv; accN.w *= inv;
    accE.x *= inv; accE.y *= inv; accE.z *= inv; accE.w *= inv;
    float* base = mean + (size_t)node * 2 * D;
    reinterpret_cast<float4*>(base)[lane] = accN;
    reinterpret_cast<float4*>(base + D)[lane] = accE;
}

// Layer 2: e1 = relu(P1[u] + Q1[node] + b1e) on the fly; mean of [h1[u], e1].
__global__ void agg2_gather_kernel(const float* __restrict__ h1, const float* __restrict__ pq,
                                   const float* __restrict__ be,
                                   const int* __restrict__ u,
                                   const int* __restrict__ row_start,
                                   const int* __restrict__ eidx,
                                   float* __restrict__ mean, int N) {
    int node = blockIdx.x * 8 + (threadIdx.x >> 5);
    int lane = threadIdx.x & 31;
    if (node >= N) return;
    int rs = row_start[node], re = row_start[node + 1];
    float4 q  = reinterpret_cast<const float4*>(pq + (size_t)node * 2 * D + D)[lane];
    float4 bb = reinterpret_cast<const float4*>(be)[lane];
    float4 qb = make_float4(q.x + bb.x, q.y + bb.y, q.z + bb.z, q.w + bb.w);
    float4 accH = make_float4(0.f, 0.f, 0.f, 0.f);
    float4 accE = make_float4(0.f, 0.f, 0.f, 0.f);
    for (int j = rs; j < re; j++) {
        int e = eidx[j];
        int su = u[e];
        float4 h = reinterpret_cast<const float4*>(h1 + (size_t)su * D)[lane];
        float4 p = reinterpret_cast<const float4*>(pq + (size_t)su * 2 * D)[lane];
        add4(accH, h);
        accE.x += fmaxf(p.x + qb.x, 0.f);
        accE.y += fmaxf(p.y + qb.y, 0.f);
        accE.z += fmaxf(p.z + qb.z, 0.f);
        accE.w += fmaxf(p.w + qb.w, 0.f);
    }
    float inv = 1.0f / fmaxf((float)(re - rs), 1.0f);
    accH.x *= inv; accH.y *= inv; accH.z *= inv; accH.w *= inv;
    accE.x *= inv; accE.y *= inv; accE.z *= inv; accE.w *= inv;
    float* base = mean + (size_t)node * 2 * D;
    reinterpret_cast<float4*>(base)[lane] = accH;
    reinterpret_cast<float4*>(base + D)[lane] = accE;
}

// Final edge output: e2 = relu(P2[u] + Q2[v] + b2e)
__global__ void edge2_kernel(const float* __restrict__ pq, const float* __restrict__ be,
                             const int* __restrict__ u, const int* __restrict__ v,
                             float* __restrict__ out_e, int E) {
    int e = blockIdx.x * 8 + (threadIdx.x >> 5);
    int lane = threadIdx.x & 31;
    if (e >= E) return;
    int su = u[e], dv = v[e];
    float4 p  = reinterpret_cast<const float4*>(pq + (size_t)su * 2 * D)[lane];
    float4 q  = reinterpret_cast<const float4*>(pq + (size_t)dv * 2 * D + D)[lane];
    float4 bb = reinterpret_cast<const float4*>(be)[lane];
    float4 o;
    o.x = fmaxf(p.x + q.x + bb.x, 0.f);
    o.y = fmaxf(p.y + q.y + bb.y, 0.f);
    o.z = fmaxf(p.z + q.z + bb.z, 0.f);
    o.w = fmaxf(p.w + q.w + bb.w, 0.f);
    reinterpret_cast<float4*>(out_e + (size_t)e * D)[lane] = o;
}

// ---------------- tf32 tensor-core GEMM for the node MLPs ----------------
// Y[r, ycol+o] = act( A(r,:) . B(o,:) + bias[o] )
// A(r,k): catmode==0 -> A0[r*128 + k]                    (K = 128)
//         catmode==1 -> k<128 ? A0[r*128+k] : A1[r*256 + (k-128)]  (K = 384)
// B row-major, leading dim ldb. gridDim.y==2 selects B column-half + ycol (PQ mode).
#define TM 128
#define KC 16
#define KSTR 20

__global__ void __launch_bounds__(256)
gemm_tf32_kernel(const float* __restrict__ A0, const float* __restrict__ A1,
                 const float* __restrict__ B, int ldb,
                 const float* __restrict__ bias, int do_relu,
                 float* __restrict__ Y, int ldy,
                 int M, int K, int catmode) {
    __shared__ uint32_t As[TM * KSTR];
    __shared__ uint32_t Bs[TM * KSTR];

    int tid = threadIdx.x;
    int lane = tid & 31;
    int warp = tid >> 5;
    int warp_m = warp & 3;
    int warp_n = warp >> 2;
    int qrow = lane >> 2;
    int qcol = lane & 3;

    int row0 = blockIdx.x * TM;
    int ycol = blockIdx.y * D;
    const float* Bsel = B + (size_t)blockIdx.y * D;

    float acc[2][8][4];
#pragma unroll
    for (int i = 0; i < 2; i++)
#pragma unroll
        for (int j = 0; j < 8; j++)
#pragma unroll
            for (int q = 0; q < 4; q++) acc[i][j][q] = 0.f;

    int lrow = tid >> 2;
    int lc4  = (tid & 3) * 4;

    for (int kc = 0; kc < K; kc += KC) {
#pragma unroll
        for (int p = 0; p < 2; p++) {
            int r = lrow + p * 64;
            int gr = row0 + r;
            float4 av = make_float4(0.f, 0.f, 0.f, 0.f);
            if (gr < M) {
                int kk = kc + lc4;
                if (!catmode || kk < D)
                    av = *reinterpret_cast<const float4*>(A0 + (size_t)gr * D + kk);
                else
                    av = *reinterpret_cast<const float4*>(A1 + (size_t)gr * 2 * D + (kk - D));
            }
            uint32_t* dst = As + r * KSTR + lc4;
            dst[0] = f2tf32(av.x); dst[1] = f2tf32(av.y);
            dst[2] = f2tf32(av.z); dst[3] = f2tf32(av.w);
        }
#pragma unroll
        for (int p = 0; p < 2; p++) {
            int o = lrow + p * 64;
            float4 bv = *reinterpret_cast<const float4*>(Bsel + (size_t)o * ldb + kc + lc4);
            uint32_t* dst = Bs + o * KSTR + lc4;
            dst[0] = f2tf32(bv.x); dst[1] = f2tf32(bv.y);
            dst[2] = f2tf32(bv.z); dst[3] = f2tf32(bv.w);
        }
        __syncthreads();

#pragma unroll
        for (int ks = 0; ks < 2; ks++) {
            int k0 = ks * 8;
            uint32_t af[2][4];
#pragma unroll
            for (int i = 0; i < 2; i++) {
                int mr = warp_m * 32 + i * 16;
                af[i][0] = As[(mr + qrow) * KSTR + k0 + qcol];
                af[i][1] = As[(mr + 8 + qrow) * KSTR + k0 + qcol];
                af[i][2] = As[(mr + qrow) * KSTR + k0 + 4 + qcol];
                af[i][3] = As[(mr + 8 + qrow) * KSTR + k0 + 4 + qcol];
            }
            uint32_t bf[8][2];
#pragma unroll
            for (int j = 0; j < 8; j++) {
                int nr = warp_n * 64 + j * 8;
                bf[j][0] = Bs[(nr + qrow) * KSTR + k0 + qcol];
                bf[j][1] = Bs[(nr + qrow) * KSTR + k0 + 4 + qcol];
            }
#pragma unroll
            for (int i = 0; i < 2; i++)
#pragma unroll
                for (int j = 0; j < 8; j++) {
                    asm volatile(
                        "mma.sync.aligned.m16n8k8.row.col.f32.tf32.tf32.f32 "
                        "{%0,%1,%2,%3}, {%4,%5,%6,%7}, {%8,%9}, {%0,%1,%2,%3};\n"
                        : "+f"(acc[i][j][0]), "+f"(acc[i][j][1]),
                          "+f"(acc[i][j][2]), "+f"(acc[i][j][3])
                        : "r"(af[i][0]), "r"(af[i][1]), "r"(af[i][2]), "r"(af[i][3]),
                          "r"(bf[j][0]), "r"(bf[j][1]));
                }
        }
        __syncthreads();
    }

#pragma unroll
    for (int i = 0; i < 2; i++) {
#pragma unroll
        for (int j = 0; j < 8; j++) {
            int col = warp_n * 64 + j * 8 + qcol * 2;
            float b0 = bias ? bias[col]     : 0.f;
            float b1 = bias ? bias[col + 1] : 0.f;
            int gr0 = row0 + warp_m * 32 + i * 16 + qrow;
            float v0 = acc[i][j][0] + b0;
            float v1 = acc[i][j][1] + b1;
            float v2 = acc[i][j][2] + b0;
            float v3 = acc[i][j][3] + b1;
            if (do_relu) {
                v0 = fmaxf(v0, 0.f); v1 = fmaxf(v1, 0.f);
                v2 = fmaxf(v2, 0.f); v3 = fmaxf(v3, 0.f);
            }
            if (gr0 < M)
                *reinterpret_cast<float2*>(Y + (size_t)gr0 * ldy + ycol + col) =
                    make_float2(v0, v1);
            if (gr0 + 8 < M)
                *reinterpret_cast<float2*>(Y + (size_t)(gr0 + 8) * ldy + ycol + col) =
                    make_float2(v2, v3);
        }
    }
}

// ---------------- launch ----------------
extern "C" void kernel_launch(void* const* d_in, const int* in_sizes, int n_in,
                              void* d_out, int out_size) {
    const float* nf  = (const float*)d_in[0];
    const float* ef  = (const float*)d_in[1];
    const int*   u   = (const int*)d_in[2];
    const int*   v   = (const int*)d_in[3];
    const float* W1a = (const float*)d_in[4];
    const float* b1a = (const float*)d_in[5];
    const float* W1e = (const float*)d_in[6];
    const float* b1e = (const float*)d_in[7];
    const float* W2a = (const float*)d_in[8];
    const float* b2a = (const float*)d_in[9];
    const float* W2e = (const float*)d_in[10];
    const float* b2e = (const float*)d_in[11];

    int N = in_sizes[0] / D;
    int E = in_sizes[2];

    float* out_h = (float*)d_out;
    float* out_e = out_h + (size_t)N * D;

    float *mean1, *mean2, *h1, *pq;
    int *icnt, *rowstart, *cursor, *eidx;
    cudaGetSymbolAddress((void**)&mean1,    g_mean1);
    cudaGetSymbolAddress((void**)&mean2,    g_mean2);
    cudaGetSymbolAddress((void**)&h1,       g_h1);
    cudaGetSymbolAddress((void**)&pq,       g_pq);
    cudaGetSymbolAddress((void**)&icnt,     g_icnt);
    cudaGetSymbolAddress((void**)&rowstart, g_rowstart);
    cudaGetSymbolAddress((void**)&cursor,   g_cursor);
    cudaGetSymbolAddress((void**)&eidx,     g_eidx);

    int nb256 = (N + 255) / 256;
    int eb256 = (E + 255) / 256;
    int nwarp = (N + 7) / 8;
    int ewarp = (E + 7) / 8;
    int mt = (N + TM - 1) / TM;
    dim3 grid1(mt, 1), grid2(mt, 2);

    // CSR build (in-edges by dst v)
    zero_icnt_kernel<<<nb256, 256>>>(icnt, N);
    hist_kernel<<<eb256, 256>>>(v, icnt, E);
    scan_kernel<<<1, 1024>>>(icnt, rowstart, cursor, N);
    fill_kernel<<<eb256, 256>>>(v, cursor, eidx, E);

    // layer 1
    agg1_gather_kernel<<<nwarp, 256>>>(nf, ef, u, rowstart, eidx, mean1, N);
    gemm_tf32_kernel<<<grid1, 256>>>(nf, mean1, W1a, 3 * D, b1a, 1, h1, D, N, 3 * D, 1);
    gemm_tf32_kernel<<<grid2, 256>>>(h1, nullptr, W1e, 2 * D, nullptr, 0, pq, 2 * D, N, D, 0);

    // layer 2
    agg2_gather_kernel<<<nwarp, 256>>>(h1, pq, b1e, u, rowstart, eidx, mean2, N);
    gemm_tf32_kernel<<<grid1, 256>>>(h1, mean2, W2a, 3 * D, b2a, 1, out_h, D, N, 3 * D, 1);
    gemm_tf32_kernel<<<grid2, 256>>>(out_h, nullptr, W2e, 2 * D, nullptr, 0, pq, 2 * D, N, D, 0);
    edge2_kernel<<<ewarp, 256>>>(pq, b2e, u, v, out_e, E);
}